// round 4
// baseline (speedup 1.0000x reference)
#include <cuda_runtime.h>
#include <cuda_bf16.h>
#include <math.h>
#include <stdint.h>

// Problem dims (fixed): B=4, S=4096, DM=1024, H=16, HD=64
#define MDIM 16384   // B*S tokens
#define NDIM 1024
#define KDIM 1024

// ---------------------------------------------------------------------------
// Device scratch (no allocations allowed in kernel_launch)
// ---------------------------------------------------------------------------
__device__ __nv_bfloat16 g_xhi[(size_t)MDIM * KDIM];
__device__ __nv_bfloat16 g_xlo[(size_t)MDIM * KDIM];
__device__ __nv_bfloat16 g_whi[4ull * NDIM * KDIM];   // [Wq|Wk|Wv|Wfc]
__device__ __nv_bfloat16 g_wlo[4ull * NDIM * KDIM];
__device__ float         g_QKV[3ull * MDIM * NDIM];   // fp32 Q|K|V
__device__ __nv_bfloat16 g_ahi[(size_t)MDIM * NDIM];  // attn out hi
__device__ __nv_bfloat16 g_alo[(size_t)MDIM * NDIM];  // attn out lo

// ---------------------------------------------------------------------------
// Generic-PTX tensor core helpers (legal on plain sm_103 target)
// ---------------------------------------------------------------------------
__device__ __forceinline__ uint32_t smem_to_u32(const void* p) {
    uint32_t a;
    asm("{ .reg .u64 t; cvta.to.shared.u64 t, %1; cvt.u32.u64 %0, t; }" : "=r"(a) : "l"(p));
    return a;
}

__device__ __forceinline__ void cp_async16(uint32_t dst, const void* src) {
    asm volatile("cp.async.cg.shared.global [%0], [%1], 16;" :: "r"(dst), "l"(src) : "memory");
}
#define CP_COMMIT() asm volatile("cp.async.commit_group;" ::: "memory")
#define CP_WAIT(n)  asm volatile("cp.async.wait_group %0;" :: "n"(n) : "memory")

#define LDSM_X4(r0, r1, r2, r3, addr) \
    asm volatile("ldmatrix.sync.aligned.m8n8.x4.shared.b16 {%0,%1,%2,%3}, [%4];" \
                 : "=r"(r0), "=r"(r1), "=r"(r2), "=r"(r3) : "r"(addr))

#define MMA16816(d, a, b0, b1) \
    asm volatile("mma.sync.aligned.m16n8k16.row.col.f32.bf16.bf16.f32 " \
                 "{%0,%1,%2,%3},{%4,%5,%6,%7},{%8,%9},{%0,%1,%2,%3};" \
                 : "+f"((d)[0]), "+f"((d)[1]), "+f"((d)[2]), "+f"((d)[3]) \
                 : "r"((a)[0]), "r"((a)[1]), "r"((a)[2]), "r"((a)[3]), \
                   "r"(b0), "r"(b1))

// ---------------------------------------------------------------------------
// bf16x3 GEMM: C[m,n] = sum_k A[m,k] * B[n,k]   (both K-contiguous)
// 128x128x32 tile, 256 threads, 8 warps (4m x 2n), warp tile 32m x 64n.
// 3-stage cp.async pipeline, ONE __syncthreads per chunk.
// ---------------------------------------------------------------------------
#define ROWB 80                                   // padded row bytes (40 bf16)
#define TILE_BYTES (128 * ROWB)                   // 10240
#define STAGE_BYTES (4 * TILE_BYTES)              // 40960
#define NSTAGE 3
#define SMEM_DYN_BYTES (NSTAGE * STAGE_BYTES)     // 122880
#define OFF_AH 0
#define OFF_AL TILE_BYTES
#define OFF_BH (2 * TILE_BYTES)
#define OFF_BL (3 * TILE_BYTES)
#define NCHUNK (KDIM / 32)                        // 32

__device__ __forceinline__ void stage_load(
    uint32_t sb, const __nv_bfloat16* Ahp, const __nv_bfloat16* Alp,
    const __nv_bfloat16* Bhp, const __nv_bfloat16* Blp, int k0)
{
    const int tid = threadIdx.x;
    const int row = tid >> 1;
    const int half = tid & 1;                     // 0 or 1 -> 32B each
    const uint32_t soff = (uint32_t)row * ROWB + half * 32;
    const size_t goff = (size_t)row * KDIM + half * 16 + k0;
    cp_async16(sb + OFF_AH + soff,      Ahp + goff);
    cp_async16(sb + OFF_AH + soff + 16, Ahp + goff + 8);
    cp_async16(sb + OFF_AL + soff,      Alp + goff);
    cp_async16(sb + OFF_AL + soff + 16, Alp + goff + 8);
    cp_async16(sb + OFF_BH + soff,      Bhp + goff);
    cp_async16(sb + OFF_BH + soff + 16, Bhp + goff + 8);
    cp_async16(sb + OFF_BL + soff,      Blp + goff);
    cp_async16(sb + OFF_BL + soff + 16, Blp + goff + 8);
    CP_COMMIT();
}

__device__ void gemm_bf16x3(const __nv_bfloat16* __restrict__ Ahi,
                            const __nv_bfloat16* __restrict__ Alo,
                            const __nv_bfloat16* __restrict__ Bhi,
                            const __nv_bfloat16* __restrict__ Blo,
                            float* __restrict__ C)
{
    extern __shared__ char smem_raw[];
    const uint32_t base = smem_to_u32(smem_raw);

    const int tid = threadIdx.x;
    const int wid = tid >> 5;
    const int lane = tid & 31;
    const int warp_m = (wid & 3) * 32;            // 0,32,64,96
    const int warp_n = (wid >> 2) * 64;           // 0,64
    const int mBase = blockIdx.y * 128;
    const int nBase = blockIdx.x * 128;

    const __nv_bfloat16* Ahp = Ahi + (size_t)mBase * KDIM;
    const __nv_bfloat16* Alp = Alo + (size_t)mBase * KDIM;
    const __nv_bfloat16* Bhp = Bhi + (size_t)nBase * KDIM;
    const __nv_bfloat16* Blp = Blo + (size_t)nBase * KDIM;

    // ldmatrix per-lane relative offsets (within a tile), k-half via (lane>>4)
    uint32_t a_off[2], b_off[4];
#pragma unroll
    for (int i = 0; i < 2; i++)
        a_off[i] = (uint32_t)(warp_m + i * 16 + (lane & 15)) * ROWB + ((lane >> 4) << 4);
#pragma unroll
    for (int jj = 0; jj < 4; jj++)
        b_off[jj] = (uint32_t)(warp_n + jj * 16 + (lane & 15)) * ROWB + ((lane >> 4) << 4);

    float acc[2][8][4];
#pragma unroll
    for (int i = 0; i < 2; i++)
#pragma unroll
        for (int j = 0; j < 8; j++)
#pragma unroll
            for (int q = 0; q < 4; q++) acc[i][j][q] = 0.0f;

    // prologue: stages 0,1
    stage_load(base,               Ahp, Alp, Bhp, Blp, 0);
    stage_load(base + STAGE_BYTES, Ahp, Alp, Bhp, Blp, 32);

    int rd_stage = 0, wr_stage = 2;

#pragma unroll 1
    for (int c = 0; c < NCHUNK; c++) {
        // need group c complete; after prologue+issues, pending <= {c, c+1}
        if (c < NCHUNK - 1) { CP_WAIT(1); } else { CP_WAIT(0); }
        __syncthreads();

        // issue next load immediately (buffer wr_stage was last read at c-1,
        // protected by the barrier above)
        if (c + 2 < NCHUNK) {
            stage_load(base + wr_stage * STAGE_BYTES, Ahp, Alp, Bhp, Blp, (c + 2) * 32);
            wr_stage = (wr_stage == NSTAGE - 1) ? 0 : wr_stage + 1;
        }

        const uint32_t sb = base + rd_stage * STAGE_BYTES;
        rd_stage = (rd_stage == NSTAGE - 1) ? 0 : rd_stage + 1;

#pragma unroll
        for (int kk = 0; kk < 2; kk++) {
            const uint32_t ko = kk * 32;          // 16 bf16 = 32 bytes
            uint32_t ah[2][4], al[2][4];
#pragma unroll
            for (int i = 0; i < 2; i++) {
                LDSM_X4(ah[i][0], ah[i][1], ah[i][2], ah[i][3], sb + OFF_AH + a_off[i] + ko);
                LDSM_X4(al[i][0], al[i][1], al[i][2], al[i][3], sb + OFF_AL + a_off[i] + ko);
            }
            uint32_t bh[4][4], bl[4][4];
#pragma unroll
            for (int jj = 0; jj < 4; jj++) {
                LDSM_X4(bh[jj][0], bh[jj][1], bh[jj][2], bh[jj][3], sb + OFF_BH + b_off[jj] + ko);
                LDSM_X4(bl[jj][0], bl[jj][1], bl[jj][2], bl[jj][3], sb + OFF_BL + b_off[jj] + ko);
            }
            // term-outermost: same-acc MMAs are 16 instructions apart
#pragma unroll
            for (int i = 0; i < 2; i++)
#pragma unroll
                for (int jj = 0; jj < 4; jj++) {
                    MMA16816(acc[i][2 * jj],     ah[i], bh[jj][0], bh[jj][2]);
                    MMA16816(acc[i][2 * jj + 1], ah[i], bh[jj][1], bh[jj][3]);
                }
#pragma unroll
            for (int i = 0; i < 2; i++)
#pragma unroll
                for (int jj = 0; jj < 4; jj++) {
                    MMA16816(acc[i][2 * jj],     ah[i], bl[jj][0], bl[jj][2]);
                    MMA16816(acc[i][2 * jj + 1], ah[i], bl[jj][1], bl[jj][3]);
                }
#pragma unroll
            for (int i = 0; i < 2; i++)
#pragma unroll
                for (int jj = 0; jj < 4; jj++) {
                    MMA16816(acc[i][2 * jj],     al[i], bh[jj][0], bh[jj][2]);
                    MMA16816(acc[i][2 * jj + 1], al[i], bh[jj][1], bh[jj][3]);
                }
        }
    }

    // epilogue: fp32 store
#pragma unroll
    for (int i = 0; i < 2; i++) {
        const int r0 = mBase + warp_m + i * 16 + (lane >> 2);
#pragma unroll
        for (int j = 0; j < 8; j++) {
            const int col = nBase + warp_n + j * 8 + (lane & 3) * 2;
            *(float2*)(C + (size_t)r0 * NDIM + col) =
                make_float2(acc[i][j][0], acc[i][j][1]);
            *(float2*)(C + (size_t)(r0 + 8) * NDIM + col) =
                make_float2(acc[i][j][2], acc[i][j][3]);
        }
    }
}

__global__ void __launch_bounds__(256, 1)
qkv_mm_kernel()
{
    const int z = blockIdx.z;
    gemm_bf16x3(g_xhi, g_xlo,
                g_whi + (size_t)z * NDIM * KDIM,
                g_wlo + (size_t)z * NDIM * KDIM,
                g_QKV + (size_t)z * MDIM * NDIM);
}

__global__ void __launch_bounds__(256, 1)
fc_mm_kernel(float* __restrict__ out)
{
    gemm_bf16x3(g_ahi, g_alo,
                g_whi + 3ull * NDIM * KDIM,
                g_wlo + 3ull * NDIM * KDIM,
                out);
}

// ---------------------------------------------------------------------------
// fp32 -> bf16 hi/lo split
// ---------------------------------------------------------------------------
__device__ __forceinline__ void split1(float a, __nv_bfloat16& h, __nv_bfloat16& l) {
    h = __float2bfloat16(a);
    l = __float2bfloat16(a - __bfloat162float(h));
}

__global__ void __launch_bounds__(256)
split_kernel(const float* __restrict__ src, __nv_bfloat16* __restrict__ hi,
             __nv_bfloat16* __restrict__ lo, int n4)
{
    const int i = blockIdx.x * blockDim.x + threadIdx.x;
    if (i >= n4) return;
    float4 v = ((const float4*)src)[i];
    __nv_bfloat16 hx, hy, hz, hw, lx, ly, lz, lw;
    split1(v.x, hx, lx); split1(v.y, hy, ly);
    split1(v.z, hz, lz); split1(v.w, hw, lw);
    __nv_bfloat162* H = (__nv_bfloat162*)hi;
    __nv_bfloat162* L = (__nv_bfloat162*)lo;
    H[2 * i]     = __nv_bfloat162(hx, hy);
    H[2 * i + 1] = __nv_bfloat162(hz, hw);
    L[2 * i]     = __nv_bfloat162(lx, ly);
    L[2 * i + 1] = __nv_bfloat162(lz, lw);
}

// ---------------------------------------------------------------------------
// Per-token attention over the heads axis (16x16 per token), fp32 in,
// writes hi/lo bf16 for the fc GEMM.
// ---------------------------------------------------------------------------
__global__ void __launch_bounds__(256)
attn_kernel()
{
    const int token = blockIdx.x * 16 + (threadIdx.x >> 4);
    const int h = threadIdx.x & 15;

    const float4* Q4 = (const float4*)(g_QKV) + (size_t)token * 256 + h * 16;
    const float4* K4 = (const float4*)(g_QKV + (size_t)MDIM * NDIM) + (size_t)token * 256;
    const float4* V4 = (const float4*)(g_QKV + 2ull * MDIM * NDIM) + (size_t)token * 256;

    float4 q[16];
#pragma unroll
    for (int i = 0; i < 16; i++) q[i] = Q4[i];

    float s[16];
#pragma unroll
    for (int t = 0; t < 16; t++) {
        float acc = 0.0f;
#pragma unroll
        for (int dd = 0; dd < 16; dd++) {
            float4 kv = __ldg(&K4[t * 16 + dd]);
            acc = fmaf(q[dd].x, kv.x, acc);
            acc = fmaf(q[dd].y, kv.y, acc);
            acc = fmaf(q[dd].z, kv.z, acc);
            acc = fmaf(q[dd].w, kv.w, acc);
        }
        s[t] = acc * 0.125f;
    }

    float mx = s[0];
#pragma unroll
    for (int t = 1; t < 16; t++) mx = fmaxf(mx, s[t]);
    float sum = 0.0f;
#pragma unroll
    for (int t = 0; t < 16; t++) { s[t] = expf(s[t] - mx); sum += s[t]; }
    const float inv = 1.0f / sum;

    float4 o[16];
#pragma unroll
    for (int i = 0; i < 16; i++) o[i] = make_float4(0.f, 0.f, 0.f, 0.f);
#pragma unroll
    for (int t = 0; t < 16; t++) {
        const float p = s[t] * inv;
#pragma unroll
        for (int dd = 0; dd < 16; dd++) {
            float4 vv = __ldg(&V4[t * 16 + dd]);
            o[dd].x = fmaf(p, vv.x, o[dd].x);
            o[dd].y = fmaf(p, vv.y, o[dd].y);
            o[dd].z = fmaf(p, vv.z, o[dd].z);
            o[dd].w = fmaf(p, vv.w, o[dd].w);
        }
    }

    const size_t obase = (size_t)token * NDIM + h * 64;
    __nv_bfloat162* OH = (__nv_bfloat162*)(g_ahi + obase);
    __nv_bfloat162* OL = (__nv_bfloat162*)(g_alo + obase);
#pragma unroll
    for (int i = 0; i < 16; i++) {
        __nv_bfloat16 hx, hy, hz, hw, lx, ly, lz, lw;
        split1(o[i].x, hx, lx); split1(o[i].y, hy, ly);
        split1(o[i].z, hz, lz); split1(o[i].w, hw, lw);
        OH[2 * i]     = __nv_bfloat162(hx, hy);
        OH[2 * i + 1] = __nv_bfloat162(hz, hw);
        OL[2 * i]     = __nv_bfloat162(lx, ly);
        OL[2 * i + 1] = __nv_bfloat162(lz, lw);
    }
}

// ---------------------------------------------------------------------------
extern "C" void kernel_launch(void* const* d_in, const int* in_sizes, int n_in,
                              void* d_out, int out_size)
{
    const float* x   = (const float*)d_in[0];
    const float* Wq  = (const float*)d_in[1];
    const float* Wk  = (const float*)d_in[2];
    const float* Wv  = (const float*)d_in[3];
    const float* Wfc = (const float*)d_in[4];
    float* out = (float*)d_out;

    cudaFuncSetAttribute(qkv_mm_kernel, cudaFuncAttributeMaxDynamicSharedMemorySize, SMEM_DYN_BYTES);
    cudaFuncSetAttribute(fc_mm_kernel,  cudaFuncAttributeMaxDynamicSharedMemorySize, SMEM_DYN_BYTES);

    __nv_bfloat16 *xhi_p, *xlo_p, *whi_p, *wlo_p;
    cudaGetSymbolAddress((void**)&xhi_p, g_xhi);
    cudaGetSymbolAddress((void**)&xlo_p, g_xlo);
    cudaGetSymbolAddress((void**)&whi_p, g_whi);
    cudaGetSymbolAddress((void**)&wlo_p, g_wlo);

    {
        int n4 = (MDIM * KDIM) / 4;
        split_kernel<<<(n4 + 255) / 256, 256>>>(x, xhi_p, xlo_p, n4);
        int w4 = (NDIM * KDIM) / 4;
        split_kernel<<<(w4 + 255) / 256, 256>>>(Wq,  whi_p + 0ull * NDIM * KDIM, wlo_p + 0ull * NDIM * KDIM, w4);
        split_kernel<<<(w4 + 255) / 256, 256>>>(Wk,  whi_p + 1ull * NDIM * KDIM, wlo_p + 1ull * NDIM * KDIM, w4);
        split_kernel<<<(w4 + 255) / 256, 256>>>(Wv,  whi_p + 2ull * NDIM * KDIM, wlo_p + 2ull * NDIM * KDIM, w4);
        split_kernel<<<(w4 + 255) / 256, 256>>>(Wfc, whi_p + 3ull * NDIM * KDIM, wlo_p + 3ull * NDIM * KDIM, w4);
    }

    dim3 gQKV(NDIM / 128, MDIM / 128, 3);
    qkv_mm_kernel<<<gQKV, 256, SMEM_DYN_BYTES>>>();

    attn_kernel<<<MDIM / 16, 256>>>();

    dim3 gFC(NDIM / 128, MDIM / 128, 1);
    fc_mm_kernel<<<gFC, 256, SMEM_DYN_BYTES>>>(out);
}

// round 6
// speedup vs baseline: 1.4508x; 1.4508x over previous
#include <cuda_runtime.h>
#include <cuda_fp16.h>
#include <math.h>
#include <stdint.h>

// Problem dims (fixed): B=4, S=4096, DM=1024, H=16, HD=64
#define MDIM 16384   // B*S tokens
#define NDIM 1024
#define KDIM 1024

// ---------------------------------------------------------------------------
// Device scratch (no allocations allowed in kernel_launch)
// ---------------------------------------------------------------------------
__device__ __half g_xh[(size_t)MDIM * KDIM];     // x hi
__device__ __half g_xl[(size_t)MDIM * KDIM];     // x lo
__device__ __half g_wh[4ull * NDIM * KDIM];      // [Wq|Wk|Wv|Wfc] hi only
__device__ float  g_QKV[3ull * MDIM * NDIM];     // fp32 Q|K|V
__device__ __half g_ah[(size_t)MDIM * NDIM];     // attn out hi
__device__ __half g_al[(size_t)MDIM * NDIM];     // attn out lo

// ---------------------------------------------------------------------------
// Generic-PTX tensor core helpers (legal on plain sm_103 target)
// ---------------------------------------------------------------------------
__device__ __forceinline__ uint32_t smem_to_u32(const void* p) {
    uint32_t a;
    asm("{ .reg .u64 t; cvta.to.shared.u64 t, %1; cvt.u32.u64 %0, t; }" : "=r"(a) : "l"(p));
    return a;
}

__device__ __forceinline__ void cp_async16(uint32_t dst, const void* src) {
    asm volatile("cp.async.cg.shared.global [%0], [%1], 16;" :: "r"(dst), "l"(src) : "memory");
}
#define CP_COMMIT() asm volatile("cp.async.commit_group;" ::: "memory")
#define CP_WAIT(n)  asm volatile("cp.async.wait_group %0;" :: "n"(n) : "memory")

#define LDSM_X4(r0, r1, r2, r3, addr) \
    asm volatile("ldmatrix.sync.aligned.m8n8.x4.shared.b16 {%0,%1,%2,%3}, [%4];" \
                 : "=r"(r0), "=r"(r1), "=r"(r2), "=r"(r3) : "r"(addr))

#define MMAF16(d, a, b0, b1) \
    asm volatile("mma.sync.aligned.m16n8k16.row.col.f32.f16.f16.f32 " \
                 "{%0,%1,%2,%3},{%4,%5,%6,%7},{%8,%9},{%0,%1,%2,%3};" \
                 : "+f"((d)[0]), "+f"((d)[1]), "+f"((d)[2]), "+f"((d)[3]) \
                 : "r"((a)[0]), "r"((a)[1]), "r"((a)[2]), "r"((a)[3]), \
                   "r"(b0), "r"(b1))

// ---------------------------------------------------------------------------
// fp16x2 GEMM: C[m,n] = sum_k A[m,k] * B[n,k]   (both K-contiguous)
// D = Ah*Bh + Al*Bh  (A carried to 22 bits, B rounded to fp16)
// 128x128x32 tile, 256 threads, 8 warps (4m x 2n), warp tile 32m x 64n.
// 2-stage cp.async double buffer (R3-proven structure).
// ---------------------------------------------------------------------------
#define ROWB 80                                   // padded row bytes (40 fp16)
#define TILE_BYTES (128 * ROWB)                   // 10240
#define STAGE_BYTES (3 * TILE_BYTES)              // 30720 (Ah, Al, Bh)
#define SMEM_DYN_BYTES (2 * STAGE_BYTES)          // 61440
#define OFF_AH 0
#define OFF_AL TILE_BYTES
#define OFF_BH (2 * TILE_BYTES)
#define NCHUNK (KDIM / 32)                        // 32

__device__ __forceinline__ void stage_load(
    uint32_t sb, const __half* Ahp, const __half* Alp, const __half* Bhp, int k0)
{
    const int tid = threadIdx.x;
    const int row = tid >> 1;
    const int half_ = tid & 1;                    // 0 or 1 -> 32B each
    const uint32_t soff = (uint32_t)row * ROWB + half_ * 32;
    const size_t goff = (size_t)row * KDIM + half_ * 16 + k0;
    cp_async16(sb + OFF_AH + soff,      Ahp + goff);
    cp_async16(sb + OFF_AH + soff + 16, Ahp + goff + 8);
    cp_async16(sb + OFF_AL + soff,      Alp + goff);
    cp_async16(sb + OFF_AL + soff + 16, Alp + goff + 8);
    cp_async16(sb + OFF_BH + soff,      Bhp + goff);
    cp_async16(sb + OFF_BH + soff + 16, Bhp + goff + 8);
    CP_COMMIT();
}

__device__ void gemm_fp16x2(const __half* __restrict__ Ahi,
                            const __half* __restrict__ Alo,
                            const __half* __restrict__ Bhi,
                            float* __restrict__ C)
{
    extern __shared__ char smem_raw[];
    const uint32_t base = smem_to_u32(smem_raw);

    const int tid = threadIdx.x;
    const int wid = tid >> 5;
    const int lane = tid & 31;
    const int warp_m = (wid & 3) * 32;            // 0,32,64,96
    const int warp_n = (wid >> 2) * 64;           // 0,64
    const int mBase = blockIdx.y * 128;
    const int nBase = blockIdx.x * 128;

    const __half* Ahp = Ahi + (size_t)mBase * KDIM;
    const __half* Alp = Alo + (size_t)mBase * KDIM;
    const __half* Bhp = Bhi + (size_t)nBase * KDIM;

    // ldmatrix per-lane relative offsets (within a tile), k-half via (lane>>4)
    uint32_t a_off[2], b_off[4];
#pragma unroll
    for (int i = 0; i < 2; i++)
        a_off[i] = (uint32_t)(warp_m + i * 16 + (lane & 15)) * ROWB + ((lane >> 4) << 4);
#pragma unroll
    for (int jj = 0; jj < 4; jj++)
        b_off[jj] = (uint32_t)(warp_n + jj * 16 + (lane & 15)) * ROWB + ((lane >> 4) << 4);

    float acc[2][8][4];
#pragma unroll
    for (int i = 0; i < 2; i++)
#pragma unroll
        for (int j = 0; j < 8; j++)
#pragma unroll
            for (int q = 0; q < 4; q++) acc[i][j][q] = 0.0f;

    stage_load(base,               Ahp, Alp, Bhp, 0);
    stage_load(base + STAGE_BYTES, Ahp, Alp, Bhp, 32);

#pragma unroll 1
    for (int c = 0; c < NCHUNK; c++) {
        if (c < NCHUNK - 1) { CP_WAIT(1); } else { CP_WAIT(0); }
        __syncthreads();

        const uint32_t sb = base + (c & 1) * STAGE_BYTES;

#pragma unroll
        for (int kk = 0; kk < 2; kk++) {
            const uint32_t ko = kk * 32;          // 16 fp16 = 32 bytes
            uint32_t ah[2][4], al[2][4];
#pragma unroll
            for (int i = 0; i < 2; i++) {
                LDSM_X4(ah[i][0], ah[i][1], ah[i][2], ah[i][3], sb + OFF_AH + a_off[i] + ko);
                LDSM_X4(al[i][0], al[i][1], al[i][2], al[i][3], sb + OFF_AL + a_off[i] + ko);
            }
            uint32_t bh[4][4];
#pragma unroll
            for (int jj = 0; jj < 4; jj++)
                LDSM_X4(bh[jj][0], bh[jj][1], bh[jj][2], bh[jj][3], sb + OFF_BH + b_off[jj] + ko);

            // hi-term sweep then lo-term sweep: same-acc MMAs 16 instrs apart
#pragma unroll
            for (int i = 0; i < 2; i++)
#pragma unroll
                for (int jj = 0; jj < 4; jj++) {
                    MMAF16(acc[i][2 * jj],     ah[i], bh[jj][0], bh[jj][2]);
                    MMAF16(acc[i][2 * jj + 1], ah[i], bh[jj][1], bh[jj][3]);
                }
#pragma unroll
            for (int i = 0; i < 2; i++)
#pragma unroll
                for (int jj = 0; jj < 4; jj++) {
                    MMAF16(acc[i][2 * jj],     al[i], bh[jj][0], bh[jj][2]);
                    MMAF16(acc[i][2 * jj + 1], al[i], bh[jj][1], bh[jj][3]);
                }
        }

        __syncthreads();
        if (c + 2 < NCHUNK)
            stage_load(base + (c & 1) * STAGE_BYTES, Ahp, Alp, Bhp, (c + 2) * 32);
    }

    // epilogue: fp32 store
#pragma unroll
    for (int i = 0; i < 2; i++) {
        const int r0 = mBase + warp_m + i * 16 + (lane >> 2);
#pragma unroll
        for (int j = 0; j < 8; j++) {
            const int col = nBase + warp_n + j * 8 + (lane & 3) * 2;
            *(float2*)(C + (size_t)r0 * NDIM + col) =
                make_float2(acc[i][j][0], acc[i][j][1]);
            *(float2*)(C + (size_t)(r0 + 8) * NDIM + col) =
                make_float2(acc[i][j][2], acc[i][j][3]);
        }
    }
}

__global__ void __launch_bounds__(256, 1)
qkv_mm_kernel()
{
    const int z = blockIdx.z;
    gemm_fp16x2(g_xh, g_xl,
                g_wh + (size_t)z * NDIM * KDIM,
                g_QKV + (size_t)z * MDIM * NDIM);
}

__global__ void __launch_bounds__(256, 1)
fc_mm_kernel(float* __restrict__ out)
{
    gemm_fp16x2(g_ah, g_al, g_wh + 3ull * NDIM * KDIM, out);
}

// ---------------------------------------------------------------------------
// fp32 -> fp16 hi/lo split (and hi-only for weights)
// ---------------------------------------------------------------------------
__device__ __forceinline__ void split1(float a, __half& h, __half& l) {
    h = __float2half_rn(a);
    l = __float2half_rn(a - __half2float(h));
}

__global__ void __launch_bounds__(256)
split_hl_kernel(const float* __restrict__ src, __half* __restrict__ hi,
                __half* __restrict__ lo, int n4)
{
    const int i = blockIdx.x * blockDim.x + threadIdx.x;
    if (i >= n4) return;
    float4 v = ((const float4*)src)[i];
    __half hx, hy, hz, hw, lx, ly, lz, lw;
    split1(v.x, hx, lx); split1(v.y, hy, ly);
    split1(v.z, hz, lz); split1(v.w, hw, lw);
    __half2* H = (__half2*)hi;
    __half2* L = (__half2*)lo;
    H[2 * i]     = __half2(hx, hy);
    H[2 * i + 1] = __half2(hz, hw);
    L[2 * i]     = __half2(lx, ly);
    L[2 * i + 1] = __half2(lz, lw);
}

__global__ void __launch_bounds__(256)
split_h_kernel(const float* __restrict__ src, __half* __restrict__ hi, int n4)
{
    const int i = blockIdx.x * blockDim.x + threadIdx.x;
    if (i >= n4) return;
    float4 v = ((const float4*)src)[i];
    __half2* H = (__half2*)hi;
    H[2 * i]     = __half2(__float2half_rn(v.x), __float2half_rn(v.y));
    H[2 * i + 1] = __half2(__float2half_rn(v.z), __float2half_rn(v.w));
}

// ---------------------------------------------------------------------------
// Per-token attention over the heads axis (16x16 per token), fp32 in,
// writes hi/lo fp16 for the fc GEMM.
// ---------------------------------------------------------------------------
__global__ void __launch_bounds__(256)
attn_kernel()
{
    const int token = blockIdx.x * 16 + (threadIdx.x >> 4);
    const int h = threadIdx.x & 15;

    const float4* Q4 = (const float4*)(g_QKV) + (size_t)token * 256 + h * 16;
    const float4* K4 = (const float4*)(g_QKV + (size_t)MDIM * NDIM) + (size_t)token * 256;
    const float4* V4 = (const float4*)(g_QKV + 2ull * MDIM * NDIM) + (size_t)token * 256;

    float4 q[16];
#pragma unroll
    for (int i = 0; i < 16; i++) q[i] = Q4[i];

    float s[16];
#pragma unroll
    for (int t = 0; t < 16; t++) {
        float acc = 0.0f;
#pragma unroll
        for (int dd = 0; dd < 16; dd++) {
            float4 kv = __ldg(&K4[t * 16 + dd]);
            acc = fmaf(q[dd].x, kv.x, acc);
            acc = fmaf(q[dd].y, kv.y, acc);
            acc = fmaf(q[dd].z, kv.z, acc);
            acc = fmaf(q[dd].w, kv.w, acc);
        }
        s[t] = acc * 0.125f;
    }

    float mx = s[0];
#pragma unroll
    for (int t = 1; t < 16; t++) mx = fmaxf(mx, s[t]);
    float sum = 0.0f;
#pragma unroll
    for (int t = 0; t < 16; t++) { s[t] = expf(s[t] - mx); sum += s[t]; }
    const float inv = 1.0f / sum;

    float4 o[16];
#pragma unroll
    for (int i = 0; i < 16; i++) o[i] = make_float4(0.f, 0.f, 0.f, 0.f);
#pragma unroll
    for (int t = 0; t < 16; t++) {
        const float p = s[t] * inv;
#pragma unroll
        for (int dd = 0; dd < 16; dd++) {
            float4 vv = __ldg(&V4[t * 16 + dd]);
            o[dd].x = fmaf(p, vv.x, o[dd].x);
            o[dd].y = fmaf(p, vv.y, o[dd].y);
            o[dd].z = fmaf(p, vv.z, o[dd].z);
            o[dd].w = fmaf(p, vv.w, o[dd].w);
        }
    }

    const size_t obase = (size_t)token * NDIM + h * 64;
    __half2* OH = (__half2*)(g_ah + obase);
    __half2* OL = (__half2*)(g_al + obase);
#pragma unroll
    for (int i = 0; i < 16; i++) {
        __half hx, hy, hz, hw, lx, ly, lz, lw;
        split1(o[i].x, hx, lx); split1(o[i].y, hy, ly);
        split1(o[i].z, hz, lz); split1(o[i].w, hw, lw);
        OH[2 * i]     = __half2(hx, hy);
        OH[2 * i + 1] = __half2(hz, hw);
        OL[2 * i]     = __half2(lx, ly);
        OL[2 * i + 1] = __half2(lz, lw);
    }
}

// ---------------------------------------------------------------------------
extern "C" void kernel_launch(void* const* d_in, const int* in_sizes, int n_in,
                              void* d_out, int out_size)
{
    const float* x   = (const float*)d_in[0];
    const float* Wq  = (const float*)d_in[1];
    const float* Wk  = (const float*)d_in[2];
    const float* Wv  = (const float*)d_in[3];
    const float* Wfc = (const float*)d_in[4];
    float* out = (float*)d_out;

    cudaFuncSetAttribute(qkv_mm_kernel, cudaFuncAttributeMaxDynamicSharedMemorySize, SMEM_DYN_BYTES);
    cudaFuncSetAttribute(fc_mm_kernel,  cudaFuncAttributeMaxDynamicSharedMemorySize, SMEM_DYN_BYTES);

    __half *xh_p, *xl_p, *wh_p;
    cudaGetSymbolAddress((void**)&xh_p, g_xh);
    cudaGetSymbolAddress((void**)&xl_p, g_xl);
    cudaGetSymbolAddress((void**)&wh_p, g_wh);

    {
        int n4 = (MDIM * KDIM) / 4;
        split_hl_kernel<<<(n4 + 255) / 256, 256>>>(x, xh_p, xl_p, n4);
        int w4 = (NDIM * KDIM) / 4;
        split_h_kernel<<<(w4 + 255) / 256, 256>>>(Wq,  wh_p + 0ull * NDIM * KDIM, w4);
        split_h_kernel<<<(w4 + 255) / 256, 256>>>(Wk,  wh_p + 1ull * NDIM * KDIM, w4);
        split_h_kernel<<<(w4 + 255) / 256, 256>>>(Wv,  wh_p + 2ull * NDIM * KDIM, w4);
        split_h_kernel<<<(w4 + 255) / 256, 256>>>(Wfc, wh_p + 3ull * NDIM * KDIM, w4);
    }

    dim3 gQKV(NDIM / 128, MDIM / 128, 3);
    qkv_mm_kernel<<<gQKV, 256, SMEM_DYN_BYTES>>>();

    attn_kernel<<<MDIM / 16, 256>>>();

    dim3 gFC(NDIM / 128, MDIM / 128, 1);
    fc_mm_kernel<<<gFC, 256, SMEM_DYN_BYTES>>>(out);
}

// round 7
// speedup vs baseline: 2.3239x; 1.6018x over previous
#include <cuda_runtime.h>
#include <cuda_fp16.h>
#include <math.h>
#include <stdint.h>

// Problem dims (fixed): B=4, S=4096, DM=1024, H=16, HD=64
#define MDIM 16384   // B*S tokens
#define NDIM 1024
#define KDIM 1024

// ---------------------------------------------------------------------------
// Device scratch (no allocations allowed in kernel_launch)
// ---------------------------------------------------------------------------
__device__ __half g_xh[(size_t)MDIM * KDIM];     // x (fp16)
__device__ __half g_wh[4ull * NDIM * KDIM];      // [Wq|Wk|Wv|Wfc] (fp16)
__device__ float  g_QKV[3ull * MDIM * NDIM];     // fp32 Q|K|V
__device__ __half g_ah[(size_t)MDIM * NDIM];     // attn out (fp16)

// ---------------------------------------------------------------------------
// Generic-PTX tensor core helpers (legal on plain sm_103 target)
// ---------------------------------------------------------------------------
__device__ __forceinline__ uint32_t smem_to_u32(const void* p) {
    uint32_t a;
    asm("{ .reg .u64 t; cvta.to.shared.u64 t, %1; cvt.u32.u64 %0, t; }" : "=r"(a) : "l"(p));
    return a;
}

__device__ __forceinline__ void cp_async16(uint32_t dst, const void* src) {
    asm volatile("cp.async.cg.shared.global [%0], [%1], 16;" :: "r"(dst), "l"(src) : "memory");
}
#define CP_COMMIT() asm volatile("cp.async.commit_group;" ::: "memory")
#define CP_WAIT(n)  asm volatile("cp.async.wait_group %0;" :: "n"(n) : "memory")

#define LDSM_X4(r0, r1, r2, r3, addr) \
    asm volatile("ldmatrix.sync.aligned.m8n8.x4.shared.b16 {%0,%1,%2,%3}, [%4];" \
                 : "=r"(r0), "=r"(r1), "=r"(r2), "=r"(r3) : "r"(addr))

#define MMAF16(d, a, b0, b1) \
    asm volatile("mma.sync.aligned.m16n8k16.row.col.f32.f16.f16.f32 " \
                 "{%0,%1,%2,%3},{%4,%5,%6,%7},{%8,%9},{%0,%1,%2,%3};" \
                 : "+f"((d)[0]), "+f"((d)[1]), "+f"((d)[2]), "+f"((d)[3]) \
                 : "r"((a)[0]), "r"((a)[1]), "r"((a)[2]), "r"((a)[3]), \
                   "r"(b0), "r"(b1))

// ---------------------------------------------------------------------------
// fp16 GEMM: C[m,n] = sum_k A[m,k] * B[n,k]   (both K-contiguous, fp32 accum)
// 128x128x32 tile, 256 threads, 8 warps (4m x 2n), warp tile 32m x 64n.
// 2-stage cp.async double buffer, 2 CTAs/SM.
// ---------------------------------------------------------------------------
#define ROWB 80                                   // padded row bytes (40 fp16)
#define TILE_BYTES (128 * ROWB)                   // 10240
#define STAGE_BYTES (2 * TILE_BYTES)              // 20480 (A, B)
#define SMEM_DYN_BYTES (2 * STAGE_BYTES)          // 40960
#define OFF_A 0
#define OFF_B TILE_BYTES
#define NCHUNK (KDIM / 32)                        // 32

__device__ __forceinline__ void stage_load(
    uint32_t sb, const __half* Ap, const __half* Bp, int k0)
{
    const int tid = threadIdx.x;
    const int row = tid >> 1;
    const int half_ = tid & 1;                    // 0 or 1 -> 32B each
    const uint32_t soff = (uint32_t)row * ROWB + half_ * 32;
    const size_t goff = (size_t)row * KDIM + half_ * 16 + k0;
    cp_async16(sb + OFF_A + soff,      Ap + goff);
    cp_async16(sb + OFF_A + soff + 16, Ap + goff + 8);
    cp_async16(sb + OFF_B + soff,      Bp + goff);
    cp_async16(sb + OFF_B + soff + 16, Bp + goff + 8);
    CP_COMMIT();
}

__device__ void gemm_fp16(const __half* __restrict__ A,
                          const __half* __restrict__ B,
                          float* __restrict__ C)
{
    extern __shared__ char smem_raw[];
    const uint32_t base = smem_to_u32(smem_raw);

    const int tid = threadIdx.x;
    const int wid = tid >> 5;
    const int lane = tid & 31;
    const int warp_m = (wid & 3) * 32;            // 0,32,64,96
    const int warp_n = (wid >> 2) * 64;           // 0,64
    const int mBase = blockIdx.y * 128;
    const int nBase = blockIdx.x * 128;

    const __half* Ap = A + (size_t)mBase * KDIM;
    const __half* Bp = B + (size_t)nBase * KDIM;

    // ldmatrix per-lane relative offsets (within a tile), k-half via (lane>>4)
    uint32_t a_off[2], b_off[4];
#pragma unroll
    for (int i = 0; i < 2; i++)
        a_off[i] = (uint32_t)(warp_m + i * 16 + (lane & 15)) * ROWB + ((lane >> 4) << 4);
#pragma unroll
    for (int jj = 0; jj < 4; jj++)
        b_off[jj] = (uint32_t)(warp_n + jj * 16 + (lane & 15)) * ROWB + ((lane >> 4) << 4);

    float acc[2][8][4];
#pragma unroll
    for (int i = 0; i < 2; i++)
#pragma unroll
        for (int j = 0; j < 8; j++)
#pragma unroll
            for (int q = 0; q < 4; q++) acc[i][j][q] = 0.0f;

    stage_load(base,               Ap, Bp, 0);
    stage_load(base + STAGE_BYTES, Ap, Bp, 32);

#pragma unroll 1
    for (int c = 0; c < NCHUNK; c++) {
        if (c < NCHUNK - 1) { CP_WAIT(1); } else { CP_WAIT(0); }
        __syncthreads();

        const uint32_t sb = base + (c & 1) * STAGE_BYTES;

#pragma unroll
        for (int kk = 0; kk < 2; kk++) {
            const uint32_t ko = kk * 32;          // 16 fp16 = 32 bytes
            uint32_t ah[2][4];
#pragma unroll
            for (int i = 0; i < 2; i++)
                LDSM_X4(ah[i][0], ah[i][1], ah[i][2], ah[i][3], sb + OFF_A + a_off[i] + ko);
            uint32_t bh[4][4];
#pragma unroll
            for (int jj = 0; jj < 4; jj++)
                LDSM_X4(bh[jj][0], bh[jj][1], bh[jj][2], bh[jj][3], sb + OFF_B + b_off[jj] + ko);

#pragma unroll
            for (int i = 0; i < 2; i++)
#pragma unroll
                for (int jj = 0; jj < 4; jj++) {
                    MMAF16(acc[i][2 * jj],     ah[i], bh[jj][0], bh[jj][2]);
                    MMAF16(acc[i][2 * jj + 1], ah[i], bh[jj][1], bh[jj][3]);
                }
        }

        __syncthreads();
        if (c + 2 < NCHUNK)
            stage_load(base + (c & 1) * STAGE_BYTES, Ap, Bp, (c + 2) * 32);
    }

    // epilogue: fp32 store
#pragma unroll
    for (int i = 0; i < 2; i++) {
        const int r0 = mBase + warp_m + i * 16 + (lane >> 2);
#pragma unroll
        for (int j = 0; j < 8; j++) {
            const int col = nBase + warp_n + j * 8 + (lane & 3) * 2;
            *(float2*)(C + (size_t)r0 * NDIM + col) =
                make_float2(acc[i][j][0], acc[i][j][1]);
            *(float2*)(C + (size_t)(r0 + 8) * NDIM + col) =
                make_float2(acc[i][j][2], acc[i][j][3]);
        }
    }
}

__global__ void __launch_bounds__(256, 2)
qkv_mm_kernel()
{
    const int z = blockIdx.z;
    gemm_fp16(g_xh,
              g_wh + (size_t)z * NDIM * KDIM,
              g_QKV + (size_t)z * MDIM * NDIM);
}

__global__ void __launch_bounds__(256, 2)
fc_mm_kernel(float* __restrict__ out)
{
    gemm_fp16(g_ah, g_wh + 3ull * NDIM * KDIM, out);
}

// ---------------------------------------------------------------------------
// fp32 -> fp16 conversion
// ---------------------------------------------------------------------------
__global__ void __launch_bounds__(256)
cvt_h_kernel(const float* __restrict__ src, __half* __restrict__ dst, int n4)
{
    const int i = blockIdx.x * blockDim.x + threadIdx.x;
    if (i >= n4) return;
    float4 v = ((const float4*)src)[i];
    __half2* H = (__half2*)dst;
    H[2 * i]     = __half2(__float2half_rn(v.x), __float2half_rn(v.y));
    H[2 * i + 1] = __half2(__float2half_rn(v.z), __float2half_rn(v.w));
}

// ---------------------------------------------------------------------------
// Per-token attention over the heads axis (16x16 per token), fp32 in,
// writes fp16 for the fc GEMM.
// ---------------------------------------------------------------------------
__global__ void __launch_bounds__(256)
attn_kernel()
{
    const int token = blockIdx.x * 16 + (threadIdx.x >> 4);
    const int h = threadIdx.x & 15;

    const float4* Q4 = (const float4*)(g_QKV) + (size_t)token * 256 + h * 16;
    const float4* K4 = (const float4*)(g_QKV + (size_t)MDIM * NDIM) + (size_t)token * 256;
    const float4* V4 = (const float4*)(g_QKV + 2ull * MDIM * NDIM) + (size_t)token * 256;

    float4 q[16];
#pragma unroll
    for (int i = 0; i < 16; i++) q[i] = Q4[i];

    float s[16];
#pragma unroll
    for (int t = 0; t < 16; t++) {
        float acc = 0.0f;
#pragma unroll
        for (int dd = 0; dd < 16; dd++) {
            float4 kv = __ldg(&K4[t * 16 + dd]);
            acc = fmaf(q[dd].x, kv.x, acc);
            acc = fmaf(q[dd].y, kv.y, acc);
            acc = fmaf(q[dd].z, kv.z, acc);
            acc = fmaf(q[dd].w, kv.w, acc);
        }
        s[t] = acc * 0.125f;
    }

    float mx = s[0];
#pragma unroll
    for (int t = 1; t < 16; t++) mx = fmaxf(mx, s[t]);
    float sum = 0.0f;
#pragma unroll
    for (int t = 0; t < 16; t++) { s[t] = expf(s[t] - mx); sum += s[t]; }
    const float inv = 1.0f / sum;

    float4 o[16];
#pragma unroll
    for (int i = 0; i < 16; i++) o[i] = make_float4(0.f, 0.f, 0.f, 0.f);
#pragma unroll
    for (int t = 0; t < 16; t++) {
        const float p = s[t] * inv;
#pragma unroll
        for (int dd = 0; dd < 16; dd++) {
            float4 vv = __ldg(&V4[t * 16 + dd]);
            o[dd].x = fmaf(p, vv.x, o[dd].x);
            o[dd].y = fmaf(p, vv.y, o[dd].y);
            o[dd].z = fmaf(p, vv.z, o[dd].z);
            o[dd].w = fmaf(p, vv.w, o[dd].w);
        }
    }

    const size_t obase = (size_t)token * NDIM + h * 64;
    __half2* OH = (__half2*)(g_ah + obase);
#pragma unroll
    for (int i = 0; i < 16; i++) {
        OH[2 * i]     = __half2(__float2half_rn(o[i].x), __float2half_rn(o[i].y));
        OH[2 * i + 1] = __half2(__float2half_rn(o[i].z), __float2half_rn(o[i].w));
    }
}

// ---------------------------------------------------------------------------
extern "C" void kernel_launch(void* const* d_in, const int* in_sizes, int n_in,
                              void* d_out, int out_size)
{
    const float* x   = (const float*)d_in[0];
    const float* Wq  = (const float*)d_in[1];
    const float* Wk  = (const float*)d_in[2];
    const float* Wv  = (const float*)d_in[3];
    const float* Wfc = (const float*)d_in[4];
    float* out = (float*)d_out;

    cudaFuncSetAttribute(qkv_mm_kernel, cudaFuncAttributeMaxDynamicSharedMemorySize, SMEM_DYN_BYTES);
    cudaFuncSetAttribute(fc_mm_kernel,  cudaFuncAttributeMaxDynamicSharedMemorySize, SMEM_DYN_BYTES);

    __half *xh_p, *wh_p;
    cudaGetSymbolAddress((void**)&xh_p, g_xh);
    cudaGetSymbolAddress((void**)&wh_p, g_wh);

    {
        int n4 = (MDIM * KDIM) / 4;
        cvt_h_kernel<<<(n4 + 255) / 256, 256>>>(x, xh_p, n4);
        int w4 = (NDIM * KDIM) / 4;
        cvt_h_kernel<<<(w4 + 255) / 256, 256>>>(Wq,  wh_p + 0ull * NDIM * KDIM, w4);
        cvt_h_kernel<<<(w4 + 255) / 256, 256>>>(Wk,  wh_p + 1ull * NDIM * KDIM, w4);
        cvt_h_kernel<<<(w4 + 255) / 256, 256>>>(Wv,  wh_p + 2ull * NDIM * KDIM, w4);
        cvt_h_kernel<<<(w4 + 255) / 256, 256>>>(Wfc, wh_p + 3ull * NDIM * KDIM, w4);
    }

    dim3 gQKV(NDIM / 128, MDIM / 128, 3);
    qkv_mm_kernel<<<gQKV, 256, SMEM_DYN_BYTES>>>();

    attn_kernel<<<MDIM / 16, 256>>>();

    dim3 gFC(NDIM / 128, MDIM / 128, 1);
    fc_mm_kernel<<<gFC, 256, SMEM_DYN_BYTES>>>(out);
}

// round 10
// speedup vs baseline: 2.7329x; 1.1760x over previous
#include <cuda_runtime.h>
#include <cuda_fp16.h>
#include <math.h>
#include <stdint.h>

// Problem dims (fixed): B=4, S=4096, DM=1024, H=16, HD=64
#define MDIM 16384   // B*S tokens
#define NDIM 1024
#define KDIM 1024

// ---------------------------------------------------------------------------
// Device scratch (no allocations allowed in kernel_launch)
// ---------------------------------------------------------------------------
__device__ __half g_xh[(size_t)MDIM * KDIM];     // x (fp16)
__device__ __half g_wh[4ull * NDIM * KDIM];      // [Wq|Wk|Wv|Wfc] (fp16)
__device__ float  g_QKV[3ull * MDIM * NDIM];     // fp32 Q|K|V
__device__ __half g_ah[(size_t)MDIM * NDIM];     // attn out (fp16)

// ---------------------------------------------------------------------------
// Generic-PTX tensor core helpers (legal on plain sm_103 target)
// ---------------------------------------------------------------------------
__device__ __forceinline__ uint32_t smem_to_u32(const void* p) {
    uint32_t a;
    asm("{ .reg .u64 t; cvta.to.shared.u64 t, %1; cvt.u32.u64 %0, t; }" : "=r"(a) : "l"(p));
    return a;
}

__device__ __forceinline__ void cp_async16(uint32_t dst, const void* src) {
    asm volatile("cp.async.cg.shared.global [%0], [%1], 16;" :: "r"(dst), "l"(src) : "memory");
}
#define CP_COMMIT() asm volatile("cp.async.commit_group;" ::: "memory")
#define CP_WAIT(n)  asm volatile("cp.async.wait_group %0;" :: "n"(n) : "memory")

#define LDSM_X4(r0, r1, r2, r3, addr) \
    asm volatile("ldmatrix.sync.aligned.m8n8.x4.shared.b16 {%0,%1,%2,%3}, [%4];" \
                 : "=r"(r0), "=r"(r1), "=r"(r2), "=r"(r3) : "r"(addr))

#define MMAF16(d, a, b0, b1) \
    asm volatile("mma.sync.aligned.m16n8k16.row.col.f32.f16.f16.f32 " \
                 "{%0,%1,%2,%3},{%4,%5,%6,%7},{%8,%9},{%0,%1,%2,%3};" \
                 : "+f"((d)[0]), "+f"((d)[1]), "+f"((d)[2]), "+f"((d)[3]) \
                 : "r"((a)[0]), "r"((a)[1]), "r"((a)[2]), "r"((a)[3]), \
                   "r"(b0), "r"(b1))

// ---------------------------------------------------------------------------
// fp16 GEMM: C[m,n] = sum_k A[m,k] * B[n,k]   (both K-contiguous, fp32 accum)
// 128x128x32 tile, 256 threads, 8 warps (4m x 2n), warp tile 32m x 64n.
// 3-stage cp.async pipeline, ONE barrier per chunk, 2 CTAs/SM.
// ---------------------------------------------------------------------------
#define ROWB 80                                   // padded row bytes (40 fp16)
#define TILE_BYTES (128 * ROWB)                   // 10240
#define STAGE_BYTES (2 * TILE_BYTES)              // 20480 (A, B)
#define NSTAGE 3
#define SMEM_DYN_BYTES (NSTAGE * STAGE_BYTES)     // 61440
#define OFF_A 0
#define OFF_B TILE_BYTES
#define NCHUNK (KDIM / 32)                        // 32

__device__ __forceinline__ void stage_load(
    uint32_t sb, const __half* Ap, const __half* Bp, int k0)
{
    const int tid = threadIdx.x;
    const int row = tid >> 1;
    const int half_ = tid & 1;                    // 0 or 1 -> 32B each
    const uint32_t soff = (uint32_t)row * ROWB + half_ * 32;
    const size_t goff = (size_t)row * KDIM + half_ * 16 + k0;
    cp_async16(sb + OFF_A + soff,      Ap + goff);
    cp_async16(sb + OFF_A + soff + 16, Ap + goff + 8);
    cp_async16(sb + OFF_B + soff,      Bp + goff);
    cp_async16(sb + OFF_B + soff + 16, Bp + goff + 8);
    CP_COMMIT();
}

__device__ void gemm_fp16(const __half* __restrict__ A,
                          const __half* __restrict__ B,
                          float* __restrict__ C)
{
    extern __shared__ char smem_raw[];
    const uint32_t base = smem_to_u32(smem_raw);

    const int tid = threadIdx.x;
    const int wid = tid >> 5;
    const int lane = tid & 31;
    const int warp_m = (wid & 3) * 32;            // 0,32,64,96
    const int warp_n = (wid >> 2) * 64;           // 0,64
    const int mBase = blockIdx.y * 128;
    const int nBase = blockIdx.x * 128;

    const __half* Ap = A + (size_t)mBase * KDIM;
    const __half* Bp = B + (size_t)nBase * KDIM;

    // ldmatrix per-lane relative offsets (within a tile), k-half via (lane>>4)
    uint32_t a_off[2], b_off[4];
#pragma unroll
    for (int i = 0; i < 2; i++)
        a_off[i] = (uint32_t)(warp_m + i * 16 + (lane & 15)) * ROWB + ((lane >> 4) << 4);
#pragma unroll
    for (int jj = 0; jj < 4; jj++)
        b_off[jj] = (uint32_t)(warp_n + jj * 16 + (lane & 15)) * ROWB + ((lane >> 4) << 4);

    float acc[2][8][4];
#pragma unroll
    for (int i = 0; i < 2; i++)
#pragma unroll
        for (int j = 0; j < 8; j++)
#pragma unroll
            for (int q = 0; q < 4; q++) acc[i][j][q] = 0.0f;

    stage_load(base,               Ap, Bp, 0);
    stage_load(base + STAGE_BYTES, Ap, Bp, 32);

    int rd_stage = 0, wr_stage = 2;

#pragma unroll 1
    for (int c = 0; c < NCHUNK; c++) {
        // pending groups at this point: {c, c+1} -> wait leaves at most 1
        if (c < NCHUNK - 1) { CP_WAIT(1); } else { CP_WAIT(0); }
        __syncthreads();

        const uint32_t sb = base + rd_stage * STAGE_BYTES;
        rd_stage = (rd_stage == NSTAGE - 1) ? 0 : rd_stage + 1;

#pragma unroll
        for (int kk = 0; kk < 2; kk++) {
            const uint32_t ko = kk * 32;          // 16 fp16 = 32 bytes
            uint32_t ah[2][4];
#pragma unroll
            for (int i = 0; i < 2; i++)
                LDSM_X4(ah[i][0], ah[i][1], ah[i][2], ah[i][3], sb + OFF_A + a_off[i] + ko);
            uint32_t bh[4][4];
#pragma unroll
            for (int jj = 0; jj < 4; jj++)
                LDSM_X4(bh[jj][0], bh[jj][1], bh[jj][2], bh[jj][3], sb + OFF_B + b_off[jj] + ko);

#pragma unroll
            for (int i = 0; i < 2; i++)
#pragma unroll
                for (int jj = 0; jj < 4; jj++) {
                    MMAF16(acc[i][2 * jj],     ah[i], bh[jj][0], bh[jj][2]);
                    MMAF16(acc[i][2 * jj + 1], ah[i], bh[jj][1], bh[jj][3]);
                }
        }

        // stage wr_stage was last read in iteration c-1 (protected by the
        // barrier above); safe to overwrite without a second barrier.
        if (c + 2 < NCHUNK) {
            stage_load(base + wr_stage * STAGE_BYTES, Ap, Bp, (c + 2) * 32);
            wr_stage = (wr_stage == NSTAGE - 1) ? 0 : wr_stage + 1;
        }
    }

    // epilogue: fp32 store
#pragma unroll
    for (int i = 0; i < 2; i++) {
        const int r0 = mBase + warp_m + i * 16 + (lane >> 2);
#pragma unroll
        for (int j = 0; j < 8; j++) {
            const int col = nBase + warp_n + j * 8 + (lane & 3) * 2;
            *(float2*)(C + (size_t)r0 * NDIM + col) =
                make_float2(acc[i][j][0], acc[i][j][1]);
            *(float2*)(C + (size_t)(r0 + 8) * NDIM + col) =
                make_float2(acc[i][j][2], acc[i][j][3]);
        }
    }
}

__global__ void __launch_bounds__(256, 2)
qkv_mm_kernel()
{
    const int z = blockIdx.z;
    gemm_fp16(g_xh,
              g_wh + (size_t)z * NDIM * KDIM,
              g_QKV + (size_t)z * MDIM * NDIM);
}

__global__ void __launch_bounds__(256, 2)
fc_mm_kernel(float* __restrict__ out)
{
    gemm_fp16(g_ah, g_wh + 3ull * NDIM * KDIM, out);
}

// ---------------------------------------------------------------------------
// fp32 -> fp16 conversion, all 5 tensors in one launch
// ---------------------------------------------------------------------------
#define NX4 ((long)MDIM * KDIM / 4)               // x float4 count (4M)
#define NW4 ((long)NDIM * KDIM / 4)               // per-W float4 count (256K)
#define NCVT4 (NX4 + 4 * NW4)

__global__ void __launch_bounds__(256)
cvt_all_kernel(const float* __restrict__ x,  const float* __restrict__ wq,
               const float* __restrict__ wk, const float* __restrict__ wv,
               const float* __restrict__ wfc)
{
    const long i = (long)blockIdx.x * 256 + threadIdx.x;
    if (i >= NCVT4) return;
    const float* src;
    __half2* dst;
    long j;
    if (i < NX4) {
        src = x; j = i; dst = (__half2*)g_xh;
    } else {
        const long r = i - NX4;
        const int w = (int)(r >> 18);             // NW4 = 2^18
        j = r & (NW4 - 1);
        src = (w == 0) ? wq : (w == 1) ? wk : (w == 2) ? wv : wfc;
        dst = (__half2*)(g_wh + (size_t)w * NDIM * KDIM);
    }
    float4 v = ((const float4*)src)[j];
    dst[2 * j]     = __half2(__float2half_rn(v.x), __float2half_rn(v.y));
    dst[2 * j + 1] = __half2(__float2half_rn(v.z), __float2half_rn(v.w));
}

// ---------------------------------------------------------------------------
// Per-token attention over the heads axis (16x16 per token).
// 128 threads / block, 8 tokens / block, K & V staged in smem (64 KB);
// head-group reads become LDS broadcasts.
// ---------------------------------------------------------------------------
#define ATOK 8
#define ATTN_SMEM (2 * ATOK * 1024 * 4)           // 65536

__global__ void __launch_bounds__(128)
attn_kernel()
{
    extern __shared__ float sbuf[];               // [K | V], each ATOK*1024 floats
    float4* sK4 = (float4*)sbuf;
    float4* sV4 = (float4*)(sbuf + ATOK * 1024);

    const int tid = threadIdx.x;
    const int token0 = blockIdx.x * ATOK;

    const float4* Kg = (const float4*)(g_QKV + (size_t)MDIM * NDIM) + (size_t)token0 * 256;
    const float4* Vg = (const float4*)(g_QKV + 2ull * MDIM * NDIM) + (size_t)token0 * 256;
#pragma unroll
    for (int i = 0; i < (ATOK * 256) / 128; i++) {
        sK4[tid + i * 128] = Kg[tid + i * 128];
        sV4[tid + i * 128] = Vg[tid + i * 128];
    }
    __syncthreads();

    const int lt = tid >> 4;
    const int h = tid & 15;
    const int token = token0 + lt;

    const float4* Q4 = (const float4*)(g_QKV) + (size_t)token * 256 + h * 16;
    const float4* K4 = sK4 + lt * 256;
    const float4* V4 = sV4 + lt * 256;

    float4 q[16];
#pragma unroll
    for (int i = 0; i < 16; i++) q[i] = Q4[i];

    float s[16];
#pragma unroll
    for (int t = 0; t < 16; t++) {
        float acc = 0.0f;
#pragma unroll
        for (int dd = 0; dd < 16; dd++) {
            float4 kv = K4[t * 16 + dd];
            acc = fmaf(q[dd].x, kv.x, acc);
            acc = fmaf(q[dd].y, kv.y, acc);
            acc = fmaf(q[dd].z, kv.z, acc);
            acc = fmaf(q[dd].w, kv.w, acc);
        }
        s[t] = acc * 0.125f;
    }

    float mx = s[0];
#pragma unroll
    for (int t = 1; t < 16; t++) mx = fmaxf(mx, s[t]);
    float sum = 0.0f;
#pragma unroll
    for (int t = 0; t < 16; t++) { s[t] = expf(s[t] - mx); sum += s[t]; }
    const float inv = 1.0f / sum;

    float4 o[16];
#pragma unroll
    for (int i = 0; i < 16; i++) o[i] = make_float4(0.f, 0.f, 0.f, 0.f);
#pragma unroll
    for (int t = 0; t < 16; t++) {
        const float p = s[t] * inv;
#pragma unroll
        for (int dd = 0; dd < 16; dd++) {
            float4 vv = V4[t * 16 + dd];
            o[dd].x = fmaf(p, vv.x, o[dd].x);
            o[dd].y = fmaf(p, vv.y, o[dd].y);
            o[dd].z = fmaf(p, vv.z, o[dd].z);
            o[dd].w = fmaf(p, vv.w, o[dd].w);
        }
    }

    const size_t obase = (size_t)token * NDIM + h * 64;
    __half2* OH = (__half2*)(g_ah + obase);
#pragma unroll
    for (int i = 0; i < 16; i++) {
        OH[2 * i]     = __half2(__float2half_rn(o[i].x), __float2half_rn(o[i].y));
        OH[2 * i + 1] = __half2(__float2half_rn(o[i].z), __float2half_rn(o[i].w));
    }
}

// ---------------------------------------------------------------------------
extern "C" void kernel_launch(void* const* d_in, const int* in_sizes, int n_in,
                              void* d_out, int out_size)
{
    const float* x   = (const float*)d_in[0];
    const float* Wq  = (const float*)d_in[1];
    const float* Wk  = (const float*)d_in[2];
    const float* Wv  = (const float*)d_in[3];
    const float* Wfc = (const float*)d_in[4];
    float* out = (float*)d_out;

    cudaFuncSetAttribute(qkv_mm_kernel, cudaFuncAttributeMaxDynamicSharedMemorySize, SMEM_DYN_BYTES);
    cudaFuncSetAttribute(fc_mm_kernel,  cudaFuncAttributeMaxDynamicSharedMemorySize, SMEM_DYN_BYTES);
    cudaFuncSetAttribute(attn_kernel,   cudaFuncAttributeMaxDynamicSharedMemorySize, ATTN_SMEM);

    {
        const long nblk = (NCVT4 + 255) / 256;
        cvt_all_kernel<<<(unsigned)nblk, 256>>>(x, Wq, Wk, Wv, Wfc);
    }

    dim3 gQKV(NDIM / 128, MDIM / 128, 3);
    qkv_mm_kernel<<<gQKV, 256, SMEM_DYN_BYTES>>>();

    attn_kernel<<<MDIM / ATOK, 128, ATTN_SMEM>>>();

    dim3 gFC(NDIM / 128, MDIM / 128, 1);
    fc_mm_kernel<<<gFC, 256, SMEM_DYN_BYTES>>>(out);
}